// round 4
// baseline (speedup 1.0000x reference)
#include <cuda_runtime.h>
#include <math.h>

#define IMGSZ 224
#define HW (IMGSZ*IMGSZ)     // 50176
#define NK 100
#define NP 16
#define NB 8
#define NT 196               // 14x14 tiles of 16x16 px

// ---------------- device scratch (static, no runtime alloc) ----------------
__device__ float g_A[NP*IMGSZ];                   // resize matrix [16,224]
__device__ float g_centers[NB][NK][5];            // SLIC centers
__device__ unsigned char g_labels[NB][HW];        // per-pixel labels
__device__ double g_part[NB][NT][NK][6];          // per-tile partial sums (7.5 MB)
__device__ float g_tmp[NB][NK][NP][IMGSZ][3];     // row-resized masked tiles (34.4 MB)

__device__ __forceinline__ float slic_ratio() {
    return (float)(10.0 / sqrt(224.0 * 224.0 / 100.0));
}

// ---------------- init: resize matrix + center init ----------------
__global__ void k_init(const float* __restrict__ x) {
    int b = blockIdx.x;
    int t = threadIdx.x;

    if (b == 0 && t < NP) {
        float sample = (t + 0.5f) * 14.0f - 0.5f;
        float total = 0.0f;
        for (int h = 0; h < IMGSZ; h++) {
            float d = fabsf(sample - (float)h) * (1.0f / 14.0f);
            float w = fmaxf(0.0f, 1.0f - d);
            g_A[t * IMGSZ + h] = w;
            total += w;
        }
        float inv = 1.0f / total;
        for (int h = 0; h < IMGSZ; h++) g_A[t * IMGSZ + h] *= inv;
    }

    if (t < NK) {
        const int cg[10] = {11, 33, 56, 78, 100, 123, 145, 168, 190, 212};
        int gy = t / 10, gx = t % 10;
        int h = cg[gy], w = cg[gx];
        const float* im = x + (size_t)b * 3 * HW;
        float ratio = slic_ratio();
        g_centers[b][t][0] = im[0 * HW + h * IMGSZ + w];
        g_centers[b][t][1] = im[1 * HW + h * IMGSZ + w];
        g_centers[b][t][2] = im[2 * HW + h * IMGSZ + w];
        g_centers[b][t][3] = (float)h * ratio;
        g_centers[b][t][4] = (float)w * ratio;
    }
}

// ---------------- fused assign + partial center sums, safe pruning ----------
// One block per 16x16 tile. Candidate pruning: center k is excluded iff
// rectMinSpatial2(k) > min_j rectMaxSpatial2(j) + 3  (colors in [0,1) =>
// color distance^2 <= 3). Conservative => labels identical to full argmin.
// Accumulation: NO atomics. Each warp scans its own 32 pixels; lane l owns
// candidate slot l, predicated double FMA into registers; fixed-order combine
// across warps => bit-deterministic partials identical to a serial double sum.
__global__ __launch_bounds__(256) void k_assign_tile(const float* __restrict__ x,
                                                     int accumulate) {
    __shared__ float scen[NK][5];
    __shared__ float scen2[NK];
    __shared__ unsigned char scand[NK];
    __shared__ unsigned int bal[8];
    __shared__ int sminbits;
    __shared__ float sf[5][256];
    __shared__ unsigned char slab[256];
    __shared__ double sacc[8][32][6];

    int tile = blockIdx.x, b = blockIdx.y, t = threadIdx.x;
    int lane = t & 31, warp = t >> 5;
    const float ratio = slic_ratio();
    int tr = tile / 14, tc = tile - tr * 14;

    if (t == 0) sminbits = 0x7f7fffff;   // +FLT_MAX
    __syncthreads();

    // ---- candidate prologue ----
    float rmin = 1e30f, rmax = 1e30f;
    float c0 = 0.f, c1 = 0.f, c2 = 0.f, c3 = 0.f, c4 = 0.f;
    if (t < NK) {
        c0 = g_centers[b][t][0];
        c1 = g_centers[b][t][1];
        c2 = g_centers[b][t][2];
        c3 = g_centers[b][t][3];
        c4 = g_centers[b][t][4];
        float ylo = (float)(tr * 16) * ratio, yhi = (float)(tr * 16 + 15) * ratio;
        float xlo = (float)(tc * 16) * ratio, xhi = (float)(tc * 16 + 15) * ratio;
        float dy0 = fmaxf(0.0f, fmaxf(ylo - c3, c3 - yhi));
        float dx0 = fmaxf(0.0f, fmaxf(xlo - c4, c4 - xhi));
        float dy1 = fmaxf(c3 - ylo, yhi - c3);
        float dx1 = fmaxf(c4 - xlo, xhi - c4);
        rmin = dy0 * dy0 + dx0 * dx0;
        rmax = dy1 * dy1 + dx1 * dx1;
    }
    float v = rmax;
#pragma unroll
    for (int o = 16; o; o >>= 1) v = fminf(v, __shfl_xor_sync(0xffffffffu, v, o));
    if (lane == 0) atomicMin(&sminbits, __float_as_int(v));
    __syncthreads();
    float thresh = __int_as_float(sminbits) + 3.001f;
    bool keep = (t < NK) && (rmin <= thresh);
    unsigned int m = __ballot_sync(0xffffffffu, keep);
    if (lane == 0) bal[warp] = m;
    __syncthreads();
    int slot = 0;
    if (keep) {
        slot = __popc(m & ((1u << lane) - 1u));
        for (int w = 0; w < warp; w++) slot += __popc(bal[w]);
        scand[slot] = (unsigned char)t;
        scen[slot][0] = c0; scen[slot][1] = c1; scen[slot][2] = c2;
        scen[slot][3] = c3; scen[slot][4] = c4;
        scen2[slot] = c0*c0 + c1*c1 + c2*c2 + c3*c3 + c4*c4;
    }
    __syncthreads();
    int nc = 0;
#pragma unroll
    for (int w = 0; w < 8; w++) nc += __popc(bal[w]);

    // ---- per-pixel assignment ----
    int py = tr * 16 + (t >> 4), px = tc * 16 + (t & 15);
    int i = py * IMGSZ + px;
    const float* im = x + (size_t)b * 3 * HW;
    float f0 = im[i];
    float f1 = im[HW + i];
    float f2 = im[2 * HW + i];
    float f3 = (float)py * ratio;
    float f4 = (float)px * ratio;
    float fsq = f0*f0 + f1*f1 + f2*f2 + f3*f3 + f4*f4;

    float best = 3.4e38f;
    int bs = 0;
    for (int s = 0; s < nc; s++) {
        float dot = f0 * scen[s][0];
        dot = fmaf(f1, scen[s][1], dot);
        dot = fmaf(f2, scen[s][2], dot);
        dot = fmaf(f3, scen[s][3], dot);
        dot = fmaf(f4, scen[s][4], dot);
        float d = fsq + scen2[s] - 2.0f * dot;
        if (d < best) { best = d; bs = s; }   // strict < + ascending k => first-min
    }
    int kk = scand[bs];
    g_labels[b][i] = (unsigned char)kk;

    if (!accumulate) return;

    // ---- deterministic per-candidate accumulation (no atomics) ----
    sf[0][t] = f0; sf[1][t] = f1; sf[2][t] = f2; sf[3][t] = f3; sf[4][t] = f4;
    slab[t] = (unsigned char)kk;
    __syncthreads();

    if (nc <= 32) {
        // fast path: warp w scans its own 32 pixels; lane l owns candidate l
        if (lane < nc) {
            unsigned char myk = scand[lane];
            double a0 = 0, a1 = 0, a2 = 0, a3 = 0, a4 = 0, a5 = 0;
            int base = warp * 32;
#pragma unroll 8
            for (int j = 0; j < 32; j++) {
                int p = base + j;
                double mm = (slab[p] == myk) ? 1.0 : 0.0;
                a0 += mm * (double)sf[0][p];
                a1 += mm * (double)sf[1][p];
                a2 += mm * (double)sf[2][p];
                a3 += mm * (double)sf[3][p];
                a4 += mm * (double)sf[4][p];
                a5 += mm;
            }
            sacc[warp][lane][0] = a0; sacc[warp][lane][1] = a1;
            sacc[warp][lane][2] = a2; sacc[warp][lane][3] = a3;
            sacc[warp][lane][4] = a4; sacc[warp][lane][5] = a5;
        }
        __syncthreads();
        if (t < NK) {
            double o0 = 0, o1 = 0, o2 = 0, o3 = 0, o4 = 0, o5 = 0;
            if (keep) {
#pragma unroll
                for (int w = 0; w < 8; w++) {
                    o0 += sacc[w][slot][0]; o1 += sacc[w][slot][1];
                    o2 += sacc[w][slot][2]; o3 += sacc[w][slot][3];
                    o4 += sacc[w][slot][4]; o5 += sacc[w][slot][5];
                }
            }
            double* gp = &g_part[b][tile][t][0];
            gp[0] = o0; gp[1] = o1; gp[2] = o2; gp[3] = o3; gp[4] = o4; gp[5] = o5;
        }
    } else {
        // slow path (rare): candidate thread scans all 256 pixels
        if (t < NK) {
            double o0 = 0, o1 = 0, o2 = 0, o3 = 0, o4 = 0, o5 = 0;
            if (keep) {
                unsigned char myk = (unsigned char)t;
                for (int p = 0; p < 256; p++) {
                    double mm = (slab[p] == myk) ? 1.0 : 0.0;
                    o0 += mm * (double)sf[0][p];
                    o1 += mm * (double)sf[1][p];
                    o2 += mm * (double)sf[2][p];
                    o3 += mm * (double)sf[3][p];
                    o4 += mm * (double)sf[4][p];
                    o5 += mm;
                }
            }
            double* gp = &g_part[b][tile][t][0];
            gp[0] = o0; gp[1] = o1; gp[2] = o2; gp[3] = o3; gp[4] = o4; gp[5] = o5;
        }
    }
}

// ---------------- reduce tile partials -> new centers ----------------
__global__ __launch_bounds__(224) void k_reduce() {
    int k = blockIdx.x, b = blockIdx.y, t = threadIdx.x;
    int lane = t & 31, warp = t >> 5;
    double s[6] = {0, 0, 0, 0, 0, 0};
    if (t < NT) {
        const double* p = &g_part[b][t][k][0];
#pragma unroll
        for (int j = 0; j < 6; j++) s[j] = p[j];
    }
#pragma unroll
    for (int o = 16; o; o >>= 1) {
#pragma unroll
        for (int j = 0; j < 6; j++) s[j] += __shfl_down_sync(0xffffffffu, s[j], o);
    }
    __shared__ double red[7][6];
    if (lane == 0) {
#pragma unroll
        for (int j = 0; j < 6; j++) red[warp][j] = s[j];
    }
    __syncthreads();
    if (t == 0) {
        double a[6] = {0, 0, 0, 0, 0, 0};
#pragma unroll
        for (int w = 0; w < 7; w++)
#pragma unroll
            for (int j = 0; j < 6; j++) a[j] += red[w][j];
        if (a[5] > 0.0) {
            double inv = 1.0 / a[5];
            g_centers[b][k][0] = (float)(a[0] * inv);
            g_centers[b][k][1] = (float)(a[1] * inv);
            g_centers[b][k][2] = (float)(a[2] * inv);
            g_centers[b][k][3] = (float)(a[3] * inv);
            g_centers[b][k][4] = (float)(a[4] * inv);
        }
    }
}

// ---------------- zero the tmp scratch ----------------
__global__ void k_zero_tmp() {
    size_t n4 = (size_t)NB * NK * NP * IMGSZ * 3 / 4;
    size_t i = (size_t)blockIdx.x * blockDim.x + threadIdx.x;
    if (i < n4) reinterpret_cast<float4*>(g_tmp)[i] = make_float4(0.f, 0.f, 0.f, 0.f);
}

// ---------------- stage 1: row-resize masked image (scatter by label) --------
__global__ __launch_bounds__(256) void k_stage1(const float* __restrict__ x) {
    int b = blockIdx.y;
    int i = blockIdx.x * blockDim.x + threadIdx.x;
    if (i >= HW) return;
    int h = i / IMGSZ, w = i - h * IMGSZ;
    int k = g_labels[b][i];
    const float* im = x + (size_t)b * 3 * HW;
    float r = im[i], g = im[HW + i], bl = im[2 * HW + i];

    int q0 = max(0, (int)ceilf((h - 20.5f) * (1.0f / 14.0f)));
    int q1 = min(NP - 1, (int)floorf((h + 7.5f) * (1.0f / 14.0f)));
    for (int q = q0; q <= q1; q++) {
        float wt = g_A[q * IMGSZ + h];
        if (wt != 0.0f) {
            float* dst = &g_tmp[b][k][q][w][0];
            atomicAdd(dst + 0, wt * r);
            atomicAdd(dst + 1, wt * g);
            atomicAdd(dst + 2, wt * bl);
        }
    }
}

// ---------------- stage 2: column-resize + output permutation ----------------
__global__ __launch_bounds__(64) void k_stage2(float* __restrict__ out) {
    int b = blockIdx.y;
    int kp = blockIdx.x;             // k*16 + p
    int k = kp >> 4, p = kp & 15;
    __shared__ float srow[IMGSZ * 3];
    int t = threadIdx.x;
    const float* tp = &g_tmp[b][k][p][0][0];
    for (int j = t; j < IMGSZ * 3; j += 64) srow[j] = tp[j];
    __syncthreads();
    if (t < 48) {
        int q = t / 3, c = t - q * 3;
        const float* Aq = &g_A[q * IMGSZ];
        float acc = 0.0f;
#pragma unroll 8
        for (int w = 0; w < IMGSZ; w++) acc = fmaf(Aq[w], srow[w * 3 + c], acc);
        int lin = ((k * 16 + p) * 16 + q) * 3 + c;
        int kc = lin >> 8;
        int s  = lin & 255;
        out[((size_t)b * 256 + s) * 300 + kc] = acc;
    }
}

// ---------------- launch ----------------
extern "C" void kernel_launch(void* const* d_in, const int* in_sizes, int n_in,
                              void* d_out, int out_size) {
    const float* x = (const float*)d_in[0];
    float* out = (float*)d_out;

    k_init<<<NB, 128>>>(x);

    dim3 gt(NT, NB);                    // 196 x 8
    dim3 gr(NK, NB);                    // 100 x 8
    for (int it = 0; it < 10; it++) {
        k_assign_tile<<<gt, 256>>>(x, 1);
        k_reduce<<<gr, 224>>>();
    }
    k_assign_tile<<<gt, 256>>>(x, 0);   // final labels only

    size_t n4 = (size_t)NB * NK * NP * IMGSZ * 3 / 4;
    k_zero_tmp<<<(unsigned)((n4 + 255) / 256), 256>>>();

    dim3 g1((HW + 255) / 256, NB);
    k_stage1<<<g1, 256>>>(x);

    dim3 g2(NK * NP, NB);
    k_stage2<<<g2, 64>>>(out);
}

// round 7
// speedup vs baseline: 2.6016x; 2.6016x over previous
#include <cuda_runtime.h>
#include <math.h>

#define IMGSZ 224
#define HW (IMGSZ*IMGSZ)     // 50176
#define NK 100
#define NP 16
#define NB 8
#define NT 196               // 14x14 tiles of 16x16 px

#define FIXSCALE 68719476736.0f   // 2^36
typedef unsigned long long u64;

// ---------------- device scratch (static, no runtime alloc) ----------------
__device__ float g_A[NP*IMGSZ];                   // resize matrix [16,224]
__device__ float g_centers[NB][NK][5];            // SLIC centers
__device__ unsigned char g_labels[NB][HW];        // per-pixel labels
__device__ u64 g_part[NB][NT][NK][6];             // per-tile partial sums (int64, 7.5MB)
__device__ float g_tmp[NB][NK][NP][IMGSZ][3];     // row-resized masked tiles (34.4 MB)

__device__ __forceinline__ float slic_ratio() {
    return (float)(10.0 / sqrt(224.0 * 224.0 / 100.0));
}

// ---------------- init: resize matrix + center init ----------------
__global__ void k_init(const float* __restrict__ x) {
    int b = blockIdx.x;
    int t = threadIdx.x;

    if (b == 0 && t < NP) {
        float sample = (t + 0.5f) * 14.0f - 0.5f;
        float total = 0.0f;
        for (int h = 0; h < IMGSZ; h++) {
            float d = fabsf(sample - (float)h) * (1.0f / 14.0f);
            float w = fmaxf(0.0f, 1.0f - d);
            g_A[t * IMGSZ + h] = w;
            total += w;
        }
        float inv = 1.0f / total;
        for (int h = 0; h < IMGSZ; h++) g_A[t * IMGSZ + h] *= inv;
    }

    if (t < NK) {
        const int cg[10] = {11, 33, 56, 78, 100, 123, 145, 168, 190, 212};
        int gy = t / 10, gx = t % 10;
        int h = cg[gy], w = cg[gx];
        const float* im = x + (size_t)b * 3 * HW;
        float ratio = slic_ratio();
        g_centers[b][t][0] = im[0 * HW + h * IMGSZ + w];
        g_centers[b][t][1] = im[1 * HW + h * IMGSZ + w];
        g_centers[b][t][2] = im[2 * HW + h * IMGSZ + w];
        g_centers[b][t][3] = (float)h * ratio;
        g_centers[b][t][4] = (float)w * ratio;
    }
}

// ---------------- fused assign + exact int64 partial sums ------------------
// One block per 16x16 tile. Candidate pruning: center k excluded iff
// rectMinSpatial2(k) > min_j rectMaxSpatial2(j) + 3 (colors in [0,1) =>
// color dist^2 <= 3). Conservative => labels identical to full argmin.
// Accumulation: features scaled by 2^36 and accumulated as uint64 via shared
// atomics — EXACT and order-independent => deterministic, no FP64 in hot path.
__global__ __launch_bounds__(256) void k_assign_tile(const float* __restrict__ x,
                                                     int accumulate) {
    __shared__ float scen[NK][5];
    __shared__ float scen2[NK];
    __shared__ unsigned char scand[NK];
    __shared__ unsigned int bal[8];
    __shared__ int sminbits;
    __shared__ u64 acc[NK][6];

    int tile = blockIdx.x, b = blockIdx.y, t = threadIdx.x;
    int lane = t & 31, warp = t >> 5;
    const float ratio = slic_ratio();
    int tr = tile / 14, tc = tile - tr * 14;

    if (t == 0) sminbits = 0x7f7fffff;   // +FLT_MAX
    // zero the int64 accumulators
    {
        u64* a = &acc[0][0];
        for (int j = t; j < NK * 6; j += 256) a[j] = 0ull;
    }
    __syncthreads();

    // ---- candidate prologue ----
    float rmin = 1e30f, rmax = 1e30f;
    float c0 = 0.f, c1 = 0.f, c2 = 0.f, c3 = 0.f, c4 = 0.f;
    if (t < NK) {
        c0 = g_centers[b][t][0];
        c1 = g_centers[b][t][1];
        c2 = g_centers[b][t][2];
        c3 = g_centers[b][t][3];
        c4 = g_centers[b][t][4];
        float ylo = (float)(tr * 16) * ratio, yhi = (float)(tr * 16 + 15) * ratio;
        float xlo = (float)(tc * 16) * ratio, xhi = (float)(tc * 16 + 15) * ratio;
        float dy0 = fmaxf(0.0f, fmaxf(ylo - c3, c3 - yhi));
        float dx0 = fmaxf(0.0f, fmaxf(xlo - c4, c4 - xhi));
        float dy1 = fmaxf(c3 - ylo, yhi - c3);
        float dx1 = fmaxf(c4 - xlo, xhi - c4);
        rmin = dy0 * dy0 + dx0 * dx0;
        rmax = dy1 * dy1 + dx1 * dx1;
    }
    float v = rmax;
#pragma unroll
    for (int o = 16; o; o >>= 1) v = fminf(v, __shfl_xor_sync(0xffffffffu, v, o));
    if (lane == 0) atomicMin(&sminbits, __float_as_int(v));
    __syncthreads();
    float thresh = __int_as_float(sminbits) + 3.001f;
    bool keep = (t < NK) && (rmin <= thresh);
    unsigned int m = __ballot_sync(0xffffffffu, keep);
    if (lane == 0) bal[warp] = m;
    __syncthreads();
    if (keep) {
        int slot = __popc(m & ((1u << lane) - 1u));
        for (int w = 0; w < warp; w++) slot += __popc(bal[w]);
        scand[slot] = (unsigned char)t;
        scen[slot][0] = c0; scen[slot][1] = c1; scen[slot][2] = c2;
        scen[slot][3] = c3; scen[slot][4] = c4;
        scen2[slot] = c0*c0 + c1*c1 + c2*c2 + c3*c3 + c4*c4;
    }
    __syncthreads();
    int nc = 0;
#pragma unroll
    for (int w = 0; w < 8; w++) nc += __popc(bal[w]);

    // ---- per-pixel assignment ----
    int py = tr * 16 + (t >> 4), px = tc * 16 + (t & 15);
    int i = py * IMGSZ + px;
    const float* im = x + (size_t)b * 3 * HW;
    float f0 = im[i];
    float f1 = im[HW + i];
    float f2 = im[2 * HW + i];
    float f3 = (float)py * ratio;
    float f4 = (float)px * ratio;
    float fsq = f0*f0 + f1*f1 + f2*f2 + f3*f3 + f4*f4;

    float best = 3.4e38f;
    int bs = 0;
    for (int s = 0; s < nc; s++) {
        float dot = f0 * scen[s][0];
        dot = fmaf(f1, scen[s][1], dot);
        dot = fmaf(f2, scen[s][2], dot);
        dot = fmaf(f3, scen[s][3], dot);
        dot = fmaf(f4, scen[s][4], dot);
        float d = fsq + scen2[s] - 2.0f * dot;
        if (d < best) { best = d; bs = s; }   // strict < + ascending k => first-min
    }
    int kk = scand[bs];
    g_labels[b][i] = (unsigned char)kk;

    if (!accumulate) return;

    // ---- exact scaled-int64 accumulation (order-independent) ----
    atomicAdd(&acc[kk][0], (u64)__float2ll_rn(f0 * FIXSCALE));
    atomicAdd(&acc[kk][1], (u64)__float2ll_rn(f1 * FIXSCALE));
    atomicAdd(&acc[kk][2], (u64)__float2ll_rn(f2 * FIXSCALE));
    atomicAdd(&acc[kk][3], (u64)__float2ll_rn(f3 * FIXSCALE));
    atomicAdd(&acc[kk][4], (u64)__float2ll_rn(f4 * FIXSCALE));
    atomicAdd(&acc[kk][5], 1ull);
    __syncthreads();

    {
        const u64* a = &acc[0][0];
        u64* gp = &g_part[b][tile][0][0];
        for (int j = t; j < NK * 6; j += 256) gp[j] = a[j];
    }
}

// ---------------- reduce tile partials -> new centers (exact int64) ---------
__global__ __launch_bounds__(224) void k_reduce() {
    int k = blockIdx.x, b = blockIdx.y, t = threadIdx.x;
    int lane = t & 31, warp = t >> 5;
    u64 s[6] = {0, 0, 0, 0, 0, 0};
    if (t < NT) {
        const u64* p = &g_part[b][t][k][0];
#pragma unroll
        for (int j = 0; j < 6; j++) s[j] = p[j];
    }
#pragma unroll
    for (int o = 16; o; o >>= 1) {
#pragma unroll
        for (int j = 0; j < 6; j++) s[j] += __shfl_down_sync(0xffffffffu, s[j], o);
    }
    __shared__ u64 red[7][6];
    if (lane == 0) {
#pragma unroll
        for (int j = 0; j < 6; j++) red[warp][j] = s[j];
    }
    __syncthreads();
    if (t == 0) {
        u64 a[6] = {0, 0, 0, 0, 0, 0};
#pragma unroll
        for (int w = 0; w < 7; w++)
#pragma unroll
            for (int j = 0; j < 6; j++) a[j] += red[w][j];
        if (a[5] > 0ull) {
            // mean = (sum / 2^36) / cnt ; ~5 fp64 ops per center, 4.8k total: negligible
            double inv = 1.0 / ((double)a[5] * 68719476736.0);
            g_centers[b][k][0] = (float)((double)a[0] * inv);
            g_centers[b][k][1] = (float)((double)a[1] * inv);
            g_centers[b][k][2] = (float)((double)a[2] * inv);
            g_centers[b][k][3] = (float)((double)a[3] * inv);
            g_centers[b][k][4] = (float)((double)a[4] * inv);
        }
    }
}

// ---------------- zero the tmp scratch ----------------
__global__ void k_zero_tmp() {
    size_t n4 = (size_t)NB * NK * NP * IMGSZ * 3 / 4;
    size_t i = (size_t)blockIdx.x * blockDim.x + threadIdx.x;
    if (i < n4) reinterpret_cast<float4*>(g_tmp)[i] = make_float4(0.f, 0.f, 0.f, 0.f);
}

// ---------------- stage 1: row-resize masked image (scatter by label) --------
__global__ __launch_bounds__(256) void k_stage1(const float* __restrict__ x) {
    int b = blockIdx.y;
    int i = blockIdx.x * blockDim.x + threadIdx.x;
    if (i >= HW) return;
    int h = i / IMGSZ, w = i - h * IMGSZ;
    int k = g_labels[b][i];
    const float* im = x + (size_t)b * 3 * HW;
    float r = im[i], g = im[HW + i], bl = im[2 * HW + i];

    int q0 = max(0, (int)ceilf((h - 20.5f) * (1.0f / 14.0f)));
    int q1 = min(NP - 1, (int)floorf((h + 7.5f) * (1.0f / 14.0f)));
    for (int q = q0; q <= q1; q++) {
        float wt = g_A[q * IMGSZ + h];
        if (wt != 0.0f) {
            float* dst = &g_tmp[b][k][q][w][0];
            atomicAdd(dst + 0, wt * r);
            atomicAdd(dst + 1, wt * g);
            atomicAdd(dst + 2, wt * bl);
        }
    }
}

// ---------------- stage 2: column-resize + output permutation ----------------
__global__ __launch_bounds__(64) void k_stage2(float* __restrict__ out) {
    int b = blockIdx.y;
    int kp = blockIdx.x;             // k*16 + p
    int k = kp >> 4, p = kp & 15;
    __shared__ float srow[IMGSZ * 3];
    int t = threadIdx.x;
    const float* tp = &g_tmp[b][k][p][0][0];
    for (int j = t; j < IMGSZ * 3; j += 64) srow[j] = tp[j];
    __syncthreads();
    if (t < 48) {
        int q = t / 3, c = t - q * 3;
        const float* Aq = &g_A[q * IMGSZ];
        float acc = 0.0f;
#pragma unroll 8
        for (int w = 0; w < IMGSZ; w++) acc = fmaf(Aq[w], srow[w * 3 + c], acc);
        int lin = ((k * 16 + p) * 16 + q) * 3 + c;
        int kc = lin >> 8;
        int s  = lin & 255;
        out[((size_t)b * 256 + s) * 300 + kc] = acc;
    }
}

// ---------------- launch ----------------
extern "C" void kernel_launch(void* const* d_in, const int* in_sizes, int n_in,
                              void* d_out, int out_size) {
    const float* x = (const float*)d_in[0];
    float* out = (float*)d_out;

    k_init<<<NB, 128>>>(x);

    dim3 gt(NT, NB);                    // 196 x 8
    dim3 gr(NK, NB);                    // 100 x 8
    for (int it = 0; it < 10; it++) {
        k_assign_tile<<<gt, 256>>>(x, 1);
        k_reduce<<<gr, 224>>>();
    }
    k_assign_tile<<<gt, 256>>>(x, 0);   // final labels only

    size_t n4 = (size_t)NB * NK * NP * IMGSZ * 3 / 4;
    k_zero_tmp<<<(unsigned)((n4 + 255) / 256), 256>>>();

    dim3 g1((HW + 255) / 256, NB);
    k_stage1<<<g1, 256>>>(x);

    dim3 g2(NK * NP, NB);
    k_stage2<<<g2, 64>>>(out);
}

// round 8
// speedup vs baseline: 9.2023x; 3.5372x over previous
#include <cuda_runtime.h>
#include <math.h>

#define IMGSZ 224
#define HW (IMGSZ*IMGSZ)     // 50176
#define NK 100
#define NP 16
#define NB 8
#define NT 196               // 14x14 tiles of 16x16 px

#define FIXSCALE 68719476736.0f   // 2^36
typedef unsigned long long u64;

// ---------------- device scratch (static, no runtime alloc) ----------------
__device__ float g_A[NP*IMGSZ];                   // resize matrix [16,224]
__device__ float g_centers[NB][NK][5];            // SLIC centers
__device__ unsigned char g_labels[NB][HW];        // per-pixel labels
__device__ u64 g_sum[NB][NK][6];                  // global int64 feature sums
__device__ float g_tmp[NB][NK][NP][IMGSZ][3];     // row-resized masked tiles (34.4 MB)

__device__ __forceinline__ float slic_ratio() {
    return (float)(10.0 / sqrt(224.0 * 224.0 / 100.0));
}

// ---------------- init: resize matrix + center init + zero sums -------------
__global__ void k_init(const float* __restrict__ x) {
    int b = blockIdx.x;
    int t = threadIdx.x;

    if (b == 0 && t < NP) {
        float sample = (t + 0.5f) * 14.0f - 0.5f;
        float total = 0.0f;
        for (int h = 0; h < IMGSZ; h++) {
            float d = fabsf(sample - (float)h) * (1.0f / 14.0f);
            float w = fmaxf(0.0f, 1.0f - d);
            g_A[t * IMGSZ + h] = w;
            total += w;
        }
        float inv = 1.0f / total;
        for (int h = 0; h < IMGSZ; h++) g_A[t * IMGSZ + h] *= inv;
    }

    // zero global sums (each of the 8 blocks zeroes its image's slice)
    {
        u64* gs = &g_sum[b][0][0];
        for (int j = t; j < NK * 6; j += blockDim.x) gs[j] = 0ull;
    }

    if (t < NK) {
        const int cg[10] = {11, 33, 56, 78, 100, 123, 145, 168, 190, 212};
        int gy = t / 10, gx = t % 10;
        int h = cg[gy], w = cg[gx];
        const float* im = x + (size_t)b * 3 * HW;
        float ratio = slic_ratio();
        g_centers[b][t][0] = im[0 * HW + h * IMGSZ + w];
        g_centers[b][t][1] = im[1 * HW + h * IMGSZ + w];
        g_centers[b][t][2] = im[2 * HW + h * IMGSZ + w];
        g_centers[b][t][3] = (float)h * ratio;
        g_centers[b][t][4] = (float)w * ratio;
    }
}

// ---------------- fused assign + warp-aggregated exact int64 sums ----------
// One block per 16x16 tile. Candidate pruning: center k excluded iff
// rectMinSpatial2(k) > min_j rectMaxSpatial2(j) + 3 (colors in [0,1) =>
// color dist^2 <= 3). Conservative => labels identical to full argmin.
// Accumulation: features scaled by 2^36 as u64. Warp-segmented butterfly
// reduction per distinct label (exact integer adds, order-independent), then
// ONE leader thread per (warp,label) does global u64 atomics. No FP64, no
// same-address atomic storms.
__global__ __launch_bounds__(256) void k_assign_tile(const float* __restrict__ x,
                                                     int accumulate) {
    __shared__ float scen[NK][5];
    __shared__ float scen2[NK];
    __shared__ unsigned char scand[NK];
    __shared__ unsigned int bal[8];
    __shared__ int sminbits;

    int tile = blockIdx.x, b = blockIdx.y, t = threadIdx.x;
    int lane = t & 31, warp = t >> 5;
    const float ratio = slic_ratio();
    int tr = tile / 14, tc = tile - tr * 14;

    if (t == 0) sminbits = 0x7f7fffff;   // +FLT_MAX
    __syncthreads();

    // ---- candidate prologue ----
    float rmin = 1e30f, rmax = 1e30f;
    float c0 = 0.f, c1 = 0.f, c2 = 0.f, c3 = 0.f, c4 = 0.f;
    if (t < NK) {
        c0 = g_centers[b][t][0];
        c1 = g_centers[b][t][1];
        c2 = g_centers[b][t][2];
        c3 = g_centers[b][t][3];
        c4 = g_centers[b][t][4];
        float ylo = (float)(tr * 16) * ratio, yhi = (float)(tr * 16 + 15) * ratio;
        float xlo = (float)(tc * 16) * ratio, xhi = (float)(tc * 16 + 15) * ratio;
        float dy0 = fmaxf(0.0f, fmaxf(ylo - c3, c3 - yhi));
        float dx0 = fmaxf(0.0f, fmaxf(xlo - c4, c4 - xhi));
        float dy1 = fmaxf(c3 - ylo, yhi - c3);
        float dx1 = fmaxf(c4 - xlo, xhi - c4);
        rmin = dy0 * dy0 + dx0 * dx0;
        rmax = dy1 * dy1 + dx1 * dx1;
    }
    float v = rmax;
#pragma unroll
    for (int o = 16; o; o >>= 1) v = fminf(v, __shfl_xor_sync(0xffffffffu, v, o));
    if (lane == 0) atomicMin(&sminbits, __float_as_int(v));
    __syncthreads();
    float thresh = __int_as_float(sminbits) + 3.001f;
    bool keep = (t < NK) && (rmin <= thresh);
    unsigned int m = __ballot_sync(0xffffffffu, keep);
    if (lane == 0) bal[warp] = m;
    __syncthreads();
    if (keep) {
        int slot = __popc(m & ((1u << lane) - 1u));
        for (int w = 0; w < warp; w++) slot += __popc(bal[w]);
        scand[slot] = (unsigned char)t;
        scen[slot][0] = c0; scen[slot][1] = c1; scen[slot][2] = c2;
        scen[slot][3] = c3; scen[slot][4] = c4;
        scen2[slot] = c0*c0 + c1*c1 + c2*c2 + c3*c3 + c4*c4;
    }
    __syncthreads();
    int nc = 0;
#pragma unroll
    for (int w = 0; w < 8; w++) nc += __popc(bal[w]);

    // ---- per-pixel assignment ----
    int py = tr * 16 + (t >> 4), px = tc * 16 + (t & 15);
    int i = py * IMGSZ + px;
    const float* im = x + (size_t)b * 3 * HW;
    float f0 = im[i];
    float f1 = im[HW + i];
    float f2 = im[2 * HW + i];
    float f3 = (float)py * ratio;
    float f4 = (float)px * ratio;
    float fsq = f0*f0 + f1*f1 + f2*f2 + f3*f3 + f4*f4;

    float best = 3.4e38f;
    int bs = 0;
    for (int s = 0; s < nc; s++) {
        float dot = f0 * scen[s][0];
        dot = fmaf(f1, scen[s][1], dot);
        dot = fmaf(f2, scen[s][2], dot);
        dot = fmaf(f3, scen[s][3], dot);
        dot = fmaf(f4, scen[s][4], dot);
        float d = fsq + scen2[s] - 2.0f * dot;
        if (d < best) { best = d; bs = s; }   // strict < + ascending k => first-min
    }
    int kk = scand[bs];
    g_labels[b][i] = (unsigned char)kk;

    if (!accumulate) return;

    // ---- warp-segmented exact int64 accumulation ----
    u64 q0 = (u64)__float2ll_rn(f0 * FIXSCALE);
    u64 q1 = (u64)__float2ll_rn(f1 * FIXSCALE);
    u64 q2 = (u64)__float2ll_rn(f2 * FIXSCALE);
    u64 q3 = (u64)__float2ll_rn(f3 * FIXSCALE);
    u64 q4 = (u64)__float2ll_rn(f4 * FIXSCALE);

    unsigned int rem = 0xffffffffu;
    while (rem) {
        int leader = __ffs((int)rem) - 1;
        int lk = __shfl_sync(0xffffffffu, kk, leader);
        bool mine = (kk == lk);
        unsigned int mm = __ballot_sync(0xffffffffu, mine);
        u64 v0 = mine ? q0 : 0ull;
        u64 v1 = mine ? q1 : 0ull;
        u64 v2 = mine ? q2 : 0ull;
        u64 v3 = mine ? q3 : 0ull;
        u64 v4 = mine ? q4 : 0ull;
#pragma unroll
        for (int o = 16; o; o >>= 1) {
            v0 += __shfl_xor_sync(0xffffffffu, v0, o);
            v1 += __shfl_xor_sync(0xffffffffu, v1, o);
            v2 += __shfl_xor_sync(0xffffffffu, v2, o);
            v3 += __shfl_xor_sync(0xffffffffu, v3, o);
            v4 += __shfl_xor_sync(0xffffffffu, v4, o);
        }
        if (lane == leader) {
            u64* gs = &g_sum[b][lk][0];
            atomicAdd(gs + 0, v0);
            atomicAdd(gs + 1, v1);
            atomicAdd(gs + 2, v2);
            atomicAdd(gs + 3, v3);
            atomicAdd(gs + 4, v4);
            atomicAdd(gs + 5, (u64)__popc(mm));
        }
        rem &= ~mm;
    }
}

// ---------------- reduce: divide sums -> new centers, re-zero sums ----------
__global__ __launch_bounds__(32) void k_reduce() {
    int k = blockIdx.x, b = blockIdx.y, t = threadIdx.x;
    if (t != 0) return;
    u64* gs = &g_sum[b][k][0];
    u64 a0 = gs[0], a1 = gs[1], a2 = gs[2], a3 = gs[3], a4 = gs[4], a5 = gs[5];
    gs[0] = 0ull; gs[1] = 0ull; gs[2] = 0ull;
    gs[3] = 0ull; gs[4] = 0ull; gs[5] = 0ull;
    if (a5 > 0ull) {
        // mean = (sum / 2^36) / cnt — exact int64 sums, tiny FP64 (spread over 800 blocks)
        double inv = 1.0 / ((double)a5 * 68719476736.0);
        g_centers[b][k][0] = (float)((double)a0 * inv);
        g_centers[b][k][1] = (float)((double)a1 * inv);
        g_centers[b][k][2] = (float)((double)a2 * inv);
        g_centers[b][k][3] = (float)((double)a3 * inv);
        g_centers[b][k][4] = (float)((double)a4 * inv);
    }
}

// ---------------- zero the tmp scratch ----------------
__global__ void k_zero_tmp() {
    size_t n4 = (size_t)NB * NK * NP * IMGSZ * 3 / 4;
    size_t i = (size_t)blockIdx.x * blockDim.x + threadIdx.x;
    if (i < n4) reinterpret_cast<float4*>(g_tmp)[i] = make_float4(0.f, 0.f, 0.f, 0.f);
}

// ---------------- stage 1: row-resize masked image (scatter by label) --------
__global__ __launch_bounds__(256) void k_stage1(const float* __restrict__ x) {
    int b = blockIdx.y;
    int i = blockIdx.x * blockDim.x + threadIdx.x;
    if (i >= HW) return;
    int h = i / IMGSZ, w = i - h * IMGSZ;
    int k = g_labels[b][i];
    const float* im = x + (size_t)b * 3 * HW;
    float r = im[i], g = im[HW + i], bl = im[2 * HW + i];

    int q0 = max(0, (int)ceilf((h - 20.5f) * (1.0f / 14.0f)));
    int q1 = min(NP - 1, (int)floorf((h + 7.5f) * (1.0f / 14.0f)));
    for (int q = q0; q <= q1; q++) {
        float wt = g_A[q * IMGSZ + h];
        if (wt != 0.0f) {
            float* dst = &g_tmp[b][k][q][w][0];
            atomicAdd(dst + 0, wt * r);
            atomicAdd(dst + 1, wt * g);
            atomicAdd(dst + 2, wt * bl);
        }
    }
}

// ---------------- stage 2: column-resize + output permutation ----------------
__global__ __launch_bounds__(64) void k_stage2(float* __restrict__ out) {
    int b = blockIdx.y;
    int kp = blockIdx.x;             // k*16 + p
    int k = kp >> 4, p = kp & 15;
    __shared__ float srow[IMGSZ * 3];
    int t = threadIdx.x;
    const float* tp = &g_tmp[b][k][p][0][0];
    for (int j = t; j < IMGSZ * 3; j += 64) srow[j] = tp[j];
    __syncthreads();
    if (t < 48) {
        int q = t / 3, c = t - q * 3;
        const float* Aq = &g_A[q * IMGSZ];
        float acc = 0.0f;
#pragma unroll 8
        for (int w = 0; w < IMGSZ; w++) acc = fmaf(Aq[w], srow[w * 3 + c], acc);
        int lin = ((k * 16 + p) * 16 + q) * 3 + c;
        int kc = lin >> 8;
        int s  = lin & 255;
        out[((size_t)b * 256 + s) * 300 + kc] = acc;
    }
}

// ---------------- launch ----------------
extern "C" void kernel_launch(void* const* d_in, const int* in_sizes, int n_in,
                              void* d_out, int out_size) {
    const float* x = (const float*)d_in[0];
    float* out = (float*)d_out;

    k_init<<<NB, 128>>>(x);

    dim3 gt(NT, NB);                    // 196 x 8
    dim3 gr(NK, NB);                    // 100 x 8
    for (int it = 0; it < 10; it++) {
        k_assign_tile<<<gt, 256>>>(x, 1);
        k_reduce<<<gr, 32>>>();
    }
    k_assign_tile<<<gt, 256>>>(x, 0);   // final labels only

    size_t n4 = (size_t)NB * NK * NP * IMGSZ * 3 / 4;
    k_zero_tmp<<<(unsigned)((n4 + 255) / 256), 256>>>();

    dim3 g1((HW + 255) / 256, NB);
    k_stage1<<<g1, 256>>>(x);

    dim3 g2(NK * NP, NB);
    k_stage2<<<g2, 64>>>(out);
}